// round 1
// baseline (speedup 1.0000x reference)
#include <cuda_runtime.h>
#include <cstdint>
#include <cstddef>

#define NTOK 8192
#define CDIM 1024
#define NEXP 8
#define DDIM 1024

#define BM 128
#define BN 64
#define BK 16
#define APAD 4
#define BPAD 8

// ---------------- scratch (device globals; no allocation) ----------------
__device__ int   g_cnt[NEXP];
__device__ int   g_list[NEXP * NTOK];          // packed token*2+k, grouped by expert
__device__ float g_probs[NTOK * 2];            // router prob per (token, slot)
__device__ float g_hidden[(size_t)NEXP * NTOK * DDIM];   // 256 MB: relu^2 activations, expert-grouped
__device__ float g_contrib[(size_t)NTOK * 2 * CDIM];     // 64 MB: per-(token,slot) scaled outputs

// ---------------- helpers ----------------
__device__ __forceinline__ uint32_t f2tf32(float f) {
    uint32_t u;
    asm("cvt.rna.tf32.f32 %0, %1;" : "=r"(u) : "f"(f));
    return u;
}

__device__ __forceinline__ void mma_tf32(float (&d)[4], const uint32_t (&a)[4], const uint32_t (&b)[2]) {
    asm volatile(
        "mma.sync.aligned.m16n8k8.row.col.f32.tf32.tf32.f32 "
        "{%0,%1,%2,%3}, {%4,%5,%6,%7}, {%8,%9}, {%0,%1,%2,%3};\n"
        : "+f"(d[0]), "+f"(d[1]), "+f"(d[2]), "+f"(d[3])
        : "r"(a[0]), "r"(a[1]), "r"(a[2]), "r"(a[3]), "r"(b[0]), "r"(b[1]));
}

// ---------------- kernel 0: zero expert counters ----------------
__global__ void zero_kernel() {
    if (threadIdx.x < NEXP) g_cnt[threadIdx.x] = 0;
}

// ---------------- kernel 1: router (1 warp per token) ----------------
__global__ __launch_bounds__(256) void router_kernel(const float* __restrict__ x,
                                                     const float* __restrict__ rw) {
    const int warp = threadIdx.x >> 5, lane = threadIdx.x & 31;
    const int t = blockIdx.x * 8 + warp;
    const float4* __restrict__ xr  = reinterpret_cast<const float4*>(x + (size_t)t * CDIM);
    const float4* __restrict__ rw4 = reinterpret_cast<const float4*>(rw);

    float acc[NEXP];
#pragma unroll
    for (int e = 0; e < NEXP; e++) acc[e] = 0.f;

#pragma unroll
    for (int it = 0; it < CDIM / 4 / 32; it++) {
        const float4 xv = xr[lane + 32 * it];
#pragma unroll
        for (int e = 0; e < NEXP; e++) {
            const float4 wv = rw4[e * (CDIM / 4) + lane + 32 * it];
            acc[e] += xv.x * wv.x + xv.y * wv.y + xv.z * wv.z + xv.w * wv.w;
        }
    }
#pragma unroll
    for (int off = 16; off; off >>= 1)
#pragma unroll
        for (int e = 0; e < NEXP; e++)
            acc[e] += __shfl_xor_sync(0xffffffffu, acc[e], off);

    if (lane == 0) {
        // top-2 with lax.top_k tie semantics (lowest index wins on ties)
        int i0 = 0; float b0 = acc[0];
#pragma unroll
        for (int e = 1; e < NEXP; e++) if (acc[e] > b0) { b0 = acc[e]; i0 = e; }
        int i1 = -1; float b1 = -3.402823e38f;
#pragma unroll
        for (int e = 0; e < NEXP; e++) if (e != i0 && acc[e] > b1) { b1 = acc[e]; i1 = e; }

        const float e1 = expf(b1 - b0);
        const float inv = 1.f / (1.f + e1);
        const float p0 = inv, p1 = e1 * inv;

        int pos0 = atomicAdd(&g_cnt[i0], 1);
        g_list[i0 * NTOK + pos0] = t * 2 + 0;
        g_probs[t * 2 + 0] = p0;
        int pos1 = atomicAdd(&g_cnt[i1], 1);
        g_list[i1 * NTOK + pos1] = t * 2 + 1;
        g_probs[t * 2 + 1] = p1;
    }
}

// ---------------- grouped GEMM (tf32 mma.sync), used for both layers ----------------
// FIRST=true : A = gathered x rows, B = w1[e] (C x D), epilogue relu^2 -> g_hidden
// FIRST=false: A = g_hidden rows,  B = w2[e] (D x C), epilogue *prob   -> g_contrib
template <bool FIRST>
__global__ __launch_bounds__(256) void moe_gemm(const float* __restrict__ x,
                                                const float* __restrict__ wall) {
    const int e = blockIdx.z;
    const int cnt = g_cnt[e];
    const int m0 = blockIdx.y * BM;
    if (m0 >= cnt) return;
    const int n0 = blockIdx.x * BN;
    const float* __restrict__ w = wall + (size_t)e * CDIM * DDIM;  // [K=1024][N=1024]

    __shared__ uint32_t As[2][BM][BK + APAD];
    __shared__ uint32_t Bs[2][BK][BN + BPAD];

    const int tid = threadIdx.x;
    const int warp = tid >> 5, lane = tid & 31;
    const int g = lane >> 2, tg = lane & 3;
    const int wm = (warp & 3) * 32;   // 4 warps along M
    const int wn = (warp >> 2) * 32;  // 2 warps along N

    // ---- per-thread global fetch mapping ----
    const int ar0 = tid >> 2;        // A rows ar0 and ar0+64, same quad
    const int aq  = tid & 3;
    const int br  = tid >> 4;        // B row 0..15
    const int bq  = tid & 15;        // B quad 0..15

    const int gr0 = m0 + ar0;
    const int gr1 = m0 + ar0 + 64;
    const int gc0 = gr0 < cnt ? gr0 : cnt - 1;  // clamp to valid row (dup data, store-guarded)
    const int gc1 = gr1 < cnt ? gr1 : cnt - 1;

    const float* apA;
    const float* apB;
    if constexpr (FIRST) {
        apA = x + (size_t)(g_list[e * NTOK + gc0] >> 1) * CDIM;
        apB = x + (size_t)(g_list[e * NTOK + gc1] >> 1) * CDIM;
    } else {
        apA = g_hidden + (size_t)(e * NTOK + gc0) * DDIM;
        apB = g_hidden + (size_t)(e * NTOK + gc1) * DDIM;
    }
    const float* bp = w + (size_t)br * DDIM + n0 + bq * 4;

    float acc[2][4][4];
#pragma unroll
    for (int i = 0; i < 2; i++)
#pragma unroll
        for (int j = 0; j < 4; j++)
#pragma unroll
            for (int q = 0; q < 4; q++) acc[i][j][q] = 0.f;

    const int NK = CDIM / BK;  // 64
    float4 fa0, fa1, fb;

    // prologue: fetch + store tile 0
    fa0 = *reinterpret_cast<const float4*>(apA + aq * 4);
    fa1 = *reinterpret_cast<const float4*>(apB + aq * 4);
    fb  = *reinterpret_cast<const float4*>(bp);
    {
        As[0][ar0][aq * 4 + 0] = f2tf32(fa0.x); As[0][ar0][aq * 4 + 1] = f2tf32(fa0.y);
        As[0][ar0][aq * 4 + 2] = f2tf32(fa0.z); As[0][ar0][aq * 4 + 3] = f2tf32(fa0.w);
        As[0][ar0 + 64][aq * 4 + 0] = f2tf32(fa1.x); As[0][ar0 + 64][aq * 4 + 1] = f2tf32(fa1.y);
        As[0][ar0 + 64][aq * 4 + 2] = f2tf32(fa1.z); As[0][ar0 + 64][aq * 4 + 3] = f2tf32(fa1.w);
        Bs[0][br][bq * 4 + 0] = f2tf32(fb.x); Bs[0][br][bq * 4 + 1] = f2tf32(fb.y);
        Bs[0][br][bq * 4 + 2] = f2tf32(fb.z); Bs[0][br][bq * 4 + 3] = f2tf32(fb.w);
    }
    __syncthreads();

#pragma unroll 1
    for (int kt = 0; kt < NK; kt++) {
        const int buf = kt & 1;
        const int k0n = (kt + 1) * BK;
        if (kt + 1 < NK) {
            fa0 = *reinterpret_cast<const float4*>(apA + k0n + aq * 4);
            fa1 = *reinterpret_cast<const float4*>(apB + k0n + aq * 4);
            fb  = *reinterpret_cast<const float4*>(bp + (size_t)k0n * DDIM);
        }
        // compute: 2 k-steps of m16n8k8
#pragma unroll
        for (int ks = 0; ks < BK; ks += 8) {
            uint32_t af[2][4];
#pragma unroll
            for (int i = 0; i < 2; i++) {
                const int r = wm + i * 16 + g;
                af[i][0] = As[buf][r][ks + tg];
                af[i][1] = As[buf][r + 8][ks + tg];
                af[i][2] = As[buf][r][ks + tg + 4];
                af[i][3] = As[buf][r + 8][ks + tg + 4];
            }
            uint32_t bf[4][2];
#pragma unroll
            for (int j = 0; j < 4; j++) {
                bf[j][0] = Bs[buf][ks + tg][wn + j * 8 + g];
                bf[j][1] = Bs[buf][ks + tg + 4][wn + j * 8 + g];
            }
#pragma unroll
            for (int i = 0; i < 2; i++)
#pragma unroll
                for (int j = 0; j < 4; j++) mma_tf32(acc[i][j], af[i], bf[j]);
        }
        if (kt + 1 < NK) {
            const int nb = buf ^ 1;
            As[nb][ar0][aq * 4 + 0] = f2tf32(fa0.x); As[nb][ar0][aq * 4 + 1] = f2tf32(fa0.y);
            As[nb][ar0][aq * 4 + 2] = f2tf32(fa0.z); As[nb][ar0][aq * 4 + 3] = f2tf32(fa0.w);
            As[nb][ar0 + 64][aq * 4 + 0] = f2tf32(fa1.x); As[nb][ar0 + 64][aq * 4 + 1] = f2tf32(fa1.y);
            As[nb][ar0 + 64][aq * 4 + 2] = f2tf32(fa1.z); As[nb][ar0 + 64][aq * 4 + 3] = f2tf32(fa1.w);
            Bs[nb][br][bq * 4 + 0] = f2tf32(fb.x); Bs[nb][br][bq * 4 + 1] = f2tf32(fb.y);
            Bs[nb][br][bq * 4 + 2] = f2tf32(fb.z); Bs[nb][br][bq * 4 + 3] = f2tf32(fb.w);
        }
        __syncthreads();
    }

    // ---- epilogue ----
#pragma unroll
    for (int i = 0; i < 2; i++) {
#pragma unroll
        for (int half = 0; half < 2; half++) {
            const int r = m0 + wm + i * 16 + g + half * 8;
            if (r < cnt) {
                if constexpr (FIRST) {
                    float* dst = &g_hidden[(size_t)(e * NTOK + r) * DDIM + n0 + wn];
#pragma unroll
                    for (int j = 0; j < 4; j++) {
                        float v0 = acc[i][j][half * 2 + 0];
                        float v1 = acc[i][j][half * 2 + 1];
                        v0 = v0 > 0.f ? v0 * v0 : 0.f;
                        v1 = v1 > 0.f ? v1 * v1 : 0.f;
                        *reinterpret_cast<float2*>(dst + j * 8 + 2 * tg) = make_float2(v0, v1);
                    }
                } else {
                    const int packed = g_list[e * NTOK + r];
                    const float p = g_probs[packed];
                    float* dst = &g_contrib[(size_t)packed * CDIM + n0 + wn];
#pragma unroll
                    for (int j = 0; j < 4; j++) {
                        const float v0 = p * acc[i][j][half * 2 + 0];
                        const float v1 = p * acc[i][j][half * 2 + 1];
                        *reinterpret_cast<float2*>(dst + j * 8 + 2 * tg) = make_float2(v0, v1);
                    }
                }
            }
        }
    }
}

// ---------------- kernel 4: combine the two expert contributions ----------------
__global__ __launch_bounds__(256) void combine_kernel(float* __restrict__ out) {
    const int v = blockIdx.x * blockDim.x + threadIdx.x;  // float4 index over [NTOK][CDIM]
    const float4* __restrict__ c4 = reinterpret_cast<const float4*>(g_contrib);
    const int t = v >> 8;        // CDIM/4 = 256 float4 per row
    const int cc = v & 255;
    const float4 a = c4[(size_t)(t * 2) * 256 + cc];
    const float4 b = c4[(size_t)(t * 2 + 1) * 256 + cc];
    reinterpret_cast<float4*>(out)[v] = make_float4(a.x + b.x, a.y + b.y, a.z + b.z, a.w + b.w);
}

// ---------------- launch ----------------
extern "C" void kernel_launch(void* const* d_in, const int* in_sizes, int n_in,
                              void* d_out, int out_size) {
    const float* x  = (const float*)d_in[0];
    const float* rw = (const float*)d_in[1];
    const float* w1 = (const float*)d_in[2];
    const float* w2 = (const float*)d_in[3];
    float* out = (float*)d_out;

    zero_kernel<<<1, 32>>>();
    router_kernel<<<NTOK / 8, 256>>>(x, rw);

    dim3 grid1(DDIM / BN, NTOK / BM, NEXP);  // (16, 64, 8); blocks past cnt[e] exit early
    moe_gemm<true><<<grid1, 256>>>(x, w1);

    dim3 grid2(CDIM / BN, NTOK / BM, NEXP);
    moe_gemm<false><<<grid2, 256>>>(nullptr, w2);

    combine_kernel<<<NTOK * CDIM / 4 / 256, 256>>>(out);
}

// round 3
// speedup vs baseline: 1.2710x; 1.2710x over previous
#include <cuda_runtime.h>
#include <cstdint>
#include <cstddef>

#define NTOK 8192
#define CDIM 1024
#define NEXP 8
#define DDIM 1024

#define BM 128
#define BN 128
#define BK 16
#define APAD 4
#define BPAD 8

// ---------------- scratch (device globals; no allocation) ----------------
__device__ int   g_cnt[NEXP];
__device__ int   g_list[NEXP * NTOK];          // packed token*2+k, grouped by expert
__device__ float g_probs[NTOK * 2];            // router prob per (token, slot)
__device__ float g_hidden[(size_t)NEXP * NTOK * DDIM];   // relu^2 activations, expert-grouped
__device__ float g_contrib[(size_t)NTOK * 2 * CDIM];     // per-(token,slot) scaled outputs

// ---------------- helpers ----------------
__device__ __forceinline__ uint32_t f2tf32(float f) {
    uint32_t u;
    asm("cvt.rna.tf32.f32 %0, %1;" : "=r"(u) : "f"(f));
    return u;
}

__device__ __forceinline__ void mma_tf32(float (&d)[4], const uint32_t (&a)[4], const uint32_t (&b)[2]) {
    asm volatile(
        "mma.sync.aligned.m16n8k8.row.col.f32.tf32.tf32.f32 "
        "{%0,%1,%2,%3}, {%4,%5,%6,%7}, {%8,%9}, {%0,%1,%2,%3};\n"
        : "+f"(d[0]), "+f"(d[1]), "+f"(d[2]), "+f"(d[3])
        : "r"(a[0]), "r"(a[1]), "r"(a[2]), "r"(a[3]), "r"(b[0]), "r"(b[1]));
}

// ---------------- kernel 0: zero expert counters ----------------
__global__ void zero_kernel() {
    if (threadIdx.x < NEXP) g_cnt[threadIdx.x] = 0;
}

// ---------------- kernel 1: router (1 warp per token) ----------------
__global__ __launch_bounds__(256) void router_kernel(const float* __restrict__ x,
                                                     const float* __restrict__ rw) {
    const int warp = threadIdx.x >> 5, lane = threadIdx.x & 31;
    const int t = blockIdx.x * 8 + warp;
    const float4* __restrict__ xr  = reinterpret_cast<const float4*>(x + (size_t)t * CDIM);
    const float4* __restrict__ rw4 = reinterpret_cast<const float4*>(rw);

    float acc[NEXP];
#pragma unroll
    for (int e = 0; e < NEXP; e++) acc[e] = 0.f;

#pragma unroll
    for (int it = 0; it < CDIM / 4 / 32; it++) {
        const float4 xv = xr[lane + 32 * it];
#pragma unroll
        for (int e = 0; e < NEXP; e++) {
            const float4 wv = rw4[e * (CDIM / 4) + lane + 32 * it];
            acc[e] += xv.x * wv.x + xv.y * wv.y + xv.z * wv.z + xv.w * wv.w;
        }
    }
#pragma unroll
    for (int off = 16; off; off >>= 1)
#pragma unroll
        for (int e = 0; e < NEXP; e++)
            acc[e] += __shfl_xor_sync(0xffffffffu, acc[e], off);

    if (lane == 0) {
        int i0 = 0; float b0 = acc[0];
#pragma unroll
        for (int e = 1; e < NEXP; e++) if (acc[e] > b0) { b0 = acc[e]; i0 = e; }
        int i1 = -1; float b1 = -3.402823e38f;
#pragma unroll
        for (int e = 0; e < NEXP; e++) if (e != i0 && acc[e] > b1) { b1 = acc[e]; i1 = e; }

        const float e1 = expf(b1 - b0);
        const float inv = 1.f / (1.f + e1);

        int pos0 = atomicAdd(&g_cnt[i0], 1);
        g_list[i0 * NTOK + pos0] = t * 2 + 0;
        g_probs[t * 2 + 0] = inv;
        int pos1 = atomicAdd(&g_cnt[i1], 1);
        g_list[i1 * NTOK + pos1] = t * 2 + 1;
        g_probs[t * 2 + 1] = e1 * inv;
    }
}

// ---------------- grouped GEMM (tf32 mma.sync), 64x64 warp tile ----------------
// FIRST=true : A = gathered x rows, B = w1[e] (C x D), epilogue relu^2 -> g_hidden
// FIRST=false: A = g_hidden rows,  B = w2[e] (D x C), epilogue *prob   -> g_contrib
template <bool FIRST>
__global__ __launch_bounds__(128) void moe_gemm(const float* __restrict__ x,
                                                const float* __restrict__ wall) {
    const int e = blockIdx.z;
    const int cnt = g_cnt[e];
    const int m0 = blockIdx.y * BM;
    if (m0 >= cnt) return;
    const int n0 = blockIdx.x * BN;
    const float* __restrict__ w = wall + (size_t)e * CDIM * DDIM;  // [K=1024][N=1024]

    __shared__ uint32_t As[2][BM][BK + APAD];
    __shared__ uint32_t Bs[2][BK][BN + BPAD];

    const int tid = threadIdx.x;
    const int warp = tid >> 5, lane = tid & 31;
    const int g = lane >> 2, tg = lane & 3;
    const int wm = (warp & 1) * 64;   // 2 warps along M
    const int wn = (warp >> 1) * 64;  // 2 warps along N

    // ---- per-thread global fetch mapping ----
    const int ar = tid >> 2;         // A rows ar, ar+32, ar+64, ar+96
    const int aq = tid & 3;          // k-quad (cols aq*4 .. aq*4+3)
    const int br = tid >> 5;         // B rows br, br+4, br+8, br+12
    const int bq = tid & 31;         // cols bq*4 .. bq*4+3

    const float* apA[4];
#pragma unroll
    for (int p = 0; p < 4; p++) {
        const int gr = m0 + ar + 32 * p;
        const int gc = gr < cnt ? gr : cnt - 1;  // clamp: dup data, store-guarded
        if constexpr (FIRST) {
            apA[p] = x + (size_t)(g_list[e * NTOK + gc] >> 1) * CDIM;
        } else {
            apA[p] = g_hidden + (size_t)(e * NTOK + gc) * DDIM;
        }
    }
    const float* bp = w + (size_t)br * DDIM + n0 + bq * 4;

    float acc[4][8][4];
#pragma unroll
    for (int i = 0; i < 4; i++)
#pragma unroll
        for (int j = 0; j < 8; j++)
#pragma unroll
            for (int q = 0; q < 4; q++) acc[i][j][q] = 0.f;

    const int NK = CDIM / BK;  // 64
    float4 fa[4], fb[4];

    // prologue: fetch + store tile 0
#pragma unroll
    for (int p = 0; p < 4; p++) fa[p] = *reinterpret_cast<const float4*>(apA[p] + aq * 4);
#pragma unroll
    for (int p = 0; p < 4; p++) fb[p] = *reinterpret_cast<const float4*>(bp + (size_t)(4 * p) * DDIM);
#pragma unroll
    for (int p = 0; p < 4; p++) {
        As[0][ar + 32 * p][aq * 4 + 0] = f2tf32(fa[p].x);
        As[0][ar + 32 * p][aq * 4 + 1] = f2tf32(fa[p].y);
        As[0][ar + 32 * p][aq * 4 + 2] = f2tf32(fa[p].z);
        As[0][ar + 32 * p][aq * 4 + 3] = f2tf32(fa[p].w);
        Bs[0][br + 4 * p][bq * 4 + 0] = f2tf32(fb[p].x);
        Bs[0][br + 4 * p][bq * 4 + 1] = f2tf32(fb[p].y);
        Bs[0][br + 4 * p][bq * 4 + 2] = f2tf32(fb[p].z);
        Bs[0][br + 4 * p][bq * 4 + 3] = f2tf32(fb[p].w);
    }
    __syncthreads();

#pragma unroll 1
    for (int kt = 0; kt < NK; kt++) {
        const int buf = kt & 1;
        const int k0n = (kt + 1) * BK;
        if (kt + 1 < NK) {
#pragma unroll
            for (int p = 0; p < 4; p++) fa[p] = *reinterpret_cast<const float4*>(apA[p] + k0n + aq * 4);
#pragma unroll
            for (int p = 0; p < 4; p++) fb[p] = *reinterpret_cast<const float4*>(bp + (size_t)(k0n + 4 * p) * DDIM);
        }
        // compute: 2 k-steps of m16n8k8 over 64x64 warp tile
#pragma unroll
        for (int ks = 0; ks < BK; ks += 8) {
            uint32_t af[4][4];
#pragma unroll
            for (int i = 0; i < 4; i++) {
                const int r = wm + i * 16 + g;
                af[i][0] = As[buf][r][ks + tg];
                af[i][1] = As[buf][r + 8][ks + tg];
                af[i][2] = As[buf][r][ks + tg + 4];
                af[i][3] = As[buf][r + 8][ks + tg + 4];
            }
            uint32_t bf[8][2];
#pragma unroll
            for (int j = 0; j < 8; j++) {
                bf[j][0] = Bs[buf][ks + tg][wn + j * 8 + g];
                bf[j][1] = Bs[buf][ks + tg + 4][wn + j * 8 + g];
            }
#pragma unroll
            for (int i = 0; i < 4; i++)
#pragma unroll
                for (int j = 0; j < 8; j++) mma_tf32(acc[i][j], af[i], bf[j]);
        }
        if (kt + 1 < NK) {
            const int nb = buf ^ 1;
#pragma unroll
            for (int p = 0; p < 4; p++) {
                As[nb][ar + 32 * p][aq * 4 + 0] = f2tf32(fa[p].x);
                As[nb][ar + 32 * p][aq * 4 + 1] = f2tf32(fa[p].y);
                As[nb][ar + 32 * p][aq * 4 + 2] = f2tf32(fa[p].z);
                As[nb][ar + 32 * p][aq * 4 + 3] = f2tf32(fa[p].w);
                Bs[nb][br + 4 * p][bq * 4 + 0] = f2tf32(fb[p].x);
                Bs[nb][br + 4 * p][bq * 4 + 1] = f2tf32(fb[p].y);
                Bs[nb][br + 4 * p][bq * 4 + 2] = f2tf32(fb[p].z);
                Bs[nb][br + 4 * p][bq * 4 + 3] = f2tf32(fb[p].w);
            }
        }
        __syncthreads();
    }

    // ---- epilogue ----
#pragma unroll
    for (int i = 0; i < 4; i++) {
#pragma unroll
        for (int half = 0; half < 2; half++) {
            const int r = m0 + wm + i * 16 + g + half * 8;
            if (r < cnt) {
                if constexpr (FIRST) {
                    float* dst = &g_hidden[(size_t)(e * NTOK + r) * DDIM + n0 + wn];
#pragma unroll
                    for (int j = 0; j < 8; j++) {
                        float v0 = acc[i][j][half * 2 + 0];
                        float v1 = acc[i][j][half * 2 + 1];
                        v0 = v0 > 0.f ? v0 * v0 : 0.f;
                        v1 = v1 > 0.f ? v1 * v1 : 0.f;
                        *reinterpret_cast<float2*>(dst + j * 8 + 2 * tg) = make_float2(v0, v1);
                    }
                } else {
                    const int packed = g_list[e * NTOK + r];
                    const float p = g_probs[packed];
                    float* dst = &g_contrib[(size_t)packed * CDIM + n0 + wn];
#pragma unroll
                    for (int j = 0; j < 8; j++) {
                        const float v0 = p * acc[i][j][half * 2 + 0];
                        const float v1 = p * acc[i][j][half * 2 + 1];
                        *reinterpret_cast<float2*>(dst + j * 8 + 2 * tg) = make_float2(v0, v1);
                    }
                }
            }
        }
    }
}

// ---------------- kernel 4: combine the two expert contributions ----------------
__global__ __launch_bounds__(256) void combine_kernel(float* __restrict__ out) {
    const int v = blockIdx.x * blockDim.x + threadIdx.x;  // float4 index over [NTOK][CDIM]
    const float4* __restrict__ c4 = reinterpret_cast<const float4*>(g_contrib);
    const int t = v >> 8;        // CDIM/4 = 256 float4 per row
    const int cc = v & 255;
    const float4 a = c4[(size_t)(t * 2) * 256 + cc];
    const float4 b = c4[(size_t)(t * 2 + 1) * 256 + cc];
    reinterpret_cast<float4*>(out)[v] = make_float4(a.x + b.x, a.y + b.y, a.z + b.z, a.w + b.w);
}

// ---------------- launch ----------------
extern "C" void kernel_launch(void* const* d_in, const int* in_sizes, int n_in,
                              void* d_out, int out_size) {
    const float* x  = (const float*)d_in[0];
    const float* rw = (const float*)d_in[1];
    const float* w1 = (const float*)d_in[2];
    const float* w2 = (const float*)d_in[3];
    float* out = (float*)d_out;

    zero_kernel<<<1, 32>>>();
    router_kernel<<<NTOK / 8, 256>>>(x, rw);

    dim3 grid1(DDIM / BN, NTOK / BM, NEXP);  // (8, 64, 8); blocks past cnt[e] exit early
    moe_gemm<true><<<grid1, 128>>>(x, w1);

    dim3 grid2(CDIM / BN, NTOK / BM, NEXP);
    moe_gemm<false><<<grid2, 128>>>(nullptr, w2);

    combine_kernel<<<NTOK * CDIM / 4 / 256, 256>>>(out);
}

// round 9
// speedup vs baseline: 1.4893x; 1.1718x over previous
#include <cuda_runtime.h>
#include <cstdint>
#include <cstddef>

#define NTOK 8192
#define CDIM 1024
#define NEXP 8
#define DDIM 1024
#define NSLOT (NTOK * 2)

#define BM 128
#define BN 128
#define BK 32
#define NKT (CDIM / BK)          // 32
#define ASTR 36                  // A smem row stride (floats)
#define BSTR 136                 // B smem row stride (floats)
#define ABYTES (BM * ASTR * 4)   // 18432
#define BBYTES (BK * BSTR * 4)   // 17408
#define STAGE_BYTES (ABYTES + BBYTES)  // 35840
#define SMEM_TOTAL (3 * STAGE_BYTES)   // 107520

// ---------------- scratch (device globals; no allocation) ----------------
__device__ int   g_cnt[NEXP];
__device__ int   g_list[NEXP * NSLOT];
__device__ float g_probs[NSLOT];
__device__ float g_xr[(size_t)NTOK * CDIM];            // tf32-rounded x
__device__ float g_w1r[(size_t)NEXP * CDIM * DDIM];    // tf32-rounded w1 [e][k=c][n=d]
__device__ float g_w2r[(size_t)NEXP * DDIM * CDIM];    // tf32-rounded w2 [e][k=d][n=c]
__device__ float g_hidden[(size_t)NSLOT * DDIM];       // relu^2, tf32-rounded, per slot
__device__ float g_contrib[(size_t)NSLOT * CDIM];      // scaled expert outputs per slot

// ---------------- helpers ----------------
__device__ __forceinline__ uint32_t f2tf32(float f) {
    uint32_t u; asm("cvt.rna.tf32.f32 %0, %1;" : "=r"(u) : "f"(f)); return u;
}
__device__ __forceinline__ uint32_t smem_u32(const void* p) {
    uint32_t a; asm("{ .reg .u64 t; cvta.to.shared.u64 t, %1; cvt.u32.u64 %0, t; }" : "=r"(a) : "l"(p));
    return a;
}
#define CP_ASYNC16(dst, src) \
    asm volatile("cp.async.cg.shared.global [%0], [%1], 16;" :: "r"(dst), "l"(src))
#define CP_COMMIT() asm volatile("cp.async.commit_group;" ::: "memory")
#define CP_WAIT1()  asm volatile("cp.async.wait_group 1;" ::: "memory")

__device__ __forceinline__ void mma_tf32(float (&d)[4], const uint32_t (&a)[4], const uint32_t (&b)[2]) {
    asm volatile(
        "mma.sync.aligned.m16n8k8.row.col.f32.tf32.tf32.f32 "
        "{%0,%1,%2,%3}, {%4,%5,%6,%7}, {%8,%9}, {%0,%1,%2,%3};\n"
        : "+f"(d[0]), "+f"(d[1]), "+f"(d[2]), "+f"(d[3])
        : "r"(a[0]), "r"(a[1]), "r"(a[2]), "r"(a[3]), "r"(b[0]), "r"(b[1]));
}

// ---------------- kernel: zero counters ----------------
__global__ void zero_kernel() {
    if (threadIdx.x < NEXP) g_cnt[threadIdx.x] = 0;
}

// ---------------- kernel: router (1 warp per token) ----------------
__global__ __launch_bounds__(256) void router_kernel(const float* __restrict__ x,
                                                     const float* __restrict__ rw) {
    const int warp = threadIdx.x >> 5, lane = threadIdx.x & 31;
    const int t = blockIdx.x * 8 + warp;
    const float4* __restrict__ xr  = reinterpret_cast<const float4*>(x + (size_t)t * CDIM);
    const float4* __restrict__ rw4 = reinterpret_cast<const float4*>(rw);

    float acc[NEXP];
#pragma unroll
    for (int e = 0; e < NEXP; e++) acc[e] = 0.f;
#pragma unroll
    for (int it = 0; it < CDIM / 4 / 32; it++) {
        const float4 xv = xr[lane + 32 * it];
#pragma unroll
        for (int e = 0; e < NEXP; e++) {
            const float4 wv = rw4[e * (CDIM / 4) + lane + 32 * it];
            acc[e] += xv.x * wv.x + xv.y * wv.y + xv.z * wv.z + xv.w * wv.w;
        }
    }
#pragma unroll
    for (int off = 16; off; off >>= 1)
#pragma unroll
        for (int e = 0; e < NEXP; e++) acc[e] += __shfl_xor_sync(0xffffffffu, acc[e], off);

    if (lane == 0) {
        int i0 = 0; float b0 = acc[0];
#pragma unroll
        for (int e = 1; e < NEXP; e++) if (acc[e] > b0) { b0 = acc[e]; i0 = e; }
        int i1 = -1; float b1 = -3.402823e38f;
#pragma unroll
        for (int e = 0; e < NEXP; e++) if (e != i0 && acc[e] > b1) { b1 = acc[e]; i1 = e; }

        const float e1 = expf(b1 - b0);
        const float inv = 1.f / (1.f + e1);

        int pos0 = atomicAdd(&g_cnt[i0], 1);
        g_list[i0 * NSLOT + pos0] = t * 2 + 0;
        g_probs[t * 2 + 0] = inv;
        int pos1 = atomicAdd(&g_cnt[i1], 1);
        g_list[i1 * NSLOT + pos1] = t * 2 + 1;
        g_probs[t * 2 + 1] = e1 * inv;
    }
}

// ---------------- prep: tf32 round x -> g_xr (device-global referenced in device code) ----
__global__ __launch_bounds__(256) void round_x_kernel(const float* __restrict__ in) {
    const size_t v = (size_t)blockIdx.x * blockDim.x + threadIdx.x;
    const float4 a = reinterpret_cast<const float4*>(in)[v];
    uint4 r;
    r.x = f2tf32(a.x); r.y = f2tf32(a.y); r.z = f2tf32(a.z); r.w = f2tf32(a.w);
    reinterpret_cast<uint4*>(g_xr)[v] = r;
}

// ---------------- prep: tf32 round weights. which=0 -> g_w1r, which=1 -> g_w2r ----
__global__ __launch_bounds__(256) void round_w_kernel(const float* __restrict__ in, int which) {
    const size_t v = (size_t)blockIdx.x * blockDim.x + threadIdx.x;
    const float4 a = reinterpret_cast<const float4*>(in)[v];
    uint4 r;
    r.x = f2tf32(a.x); r.y = f2tf32(a.y); r.z = f2tf32(a.z); r.w = f2tf32(a.w);
    float* out = which ? g_w2r : g_w1r;
    reinterpret_cast<uint4*>(out)[v] = r;
}

// ---------------- grouped GEMM: cp.async 3-stage + tf32 mma.sync ----------------
// FIRST=true : A = gathered g_xr rows,   B = g_w1r[e], relu^2+round -> g_hidden[slot]
// FIRST=false: A = g_hidden[slot] rows,  B = g_w2r[e], *prob        -> g_contrib[slot]
template <bool FIRST>
__global__ __launch_bounds__(128, 2) void moe_gemm() {
    extern __shared__ char smem[];
    const int e = blockIdx.z;
    const int cnt = g_cnt[e];
    const int m0 = blockIdx.y * BM;
    if (m0 >= cnt) return;
    const int n0 = blockIdx.x * BN;
    const float* __restrict__ w = (FIRST ? g_w1r : g_w2r) + (size_t)e * CDIM * DDIM;

    const uint32_t sb = smem_u32(smem);
    const int tid = threadIdx.x;
    const int warp = tid >> 5, lane = tid & 31;
    const int g = lane >> 2, tg = lane & 3;
    const int wm = (warp & 1) * 64;
    const int wn = (warp >> 1) * 64;

    // ---- cp.async source/dst mapping ----
    const int arow = tid >> 3, aq = tid & 7;
    const int brow = tid >> 5, bq = tid & 31;

    const float* aPtr[8];
#pragma unroll
    for (int p = 0; p < 8; p++) {
        const int gr = m0 + arow + 16 * p;
        const int gc = gr < cnt ? gr : cnt - 1;   // clamp: dup data, store-guarded
        const int packed = g_list[e * NSLOT + gc];
        if constexpr (FIRST)
            aPtr[p] = g_xr + (size_t)(packed >> 1) * CDIM + aq * 4;
        else
            aPtr[p] = g_hidden + (size_t)packed * DDIM + aq * 4;
    }
    const float* bPtr = w + (size_t)brow * DDIM + n0 + bq * 4;

    const uint32_t dA = sb + arow * (ASTR * 4) + aq * 16;
    const uint32_t dB = sb + ABYTES + brow * (BSTR * 4) + bq * 16;

#define LOAD_STAGE(kt) do {                                                         \
    const uint32_t so_ = ((kt) % 3) * STAGE_BYTES;                                  \
    _Pragma("unroll")                                                               \
    for (int p = 0; p < 8; p++)                                                     \
        CP_ASYNC16(dA + so_ + p * (16 * ASTR * 4), aPtr[p] + (size_t)(kt) * BK);    \
    _Pragma("unroll")                                                               \
    for (int p = 0; p < 8; p++)                                                     \
        CP_ASYNC16(dB + so_ + p * (4 * BSTR * 4),                                   \
                   bPtr + (size_t)((kt) * BK + 4 * p) * DDIM);                      \
} while (0)

    float acc[4][8][4];
#pragma unroll
    for (int i = 0; i < 4; i++)
#pragma unroll
        for (int j = 0; j < 8; j++)
#pragma unroll
            for (int q = 0; q < 4; q++) acc[i][j][q] = 0.f;

    LOAD_STAGE(0); CP_COMMIT();
    LOAD_STAGE(1); CP_COMMIT();

#pragma unroll 1
    for (int kt = 0; kt < NKT; kt++) {
        CP_WAIT1();            // stage kt resident
        __syncthreads();       // all warps past stage kt-1 reads
        if (kt + 2 < NKT) LOAD_STAGE(kt + 2);
        CP_COMMIT();           // one group per iteration, always

        const uint32_t* As = reinterpret_cast<const uint32_t*>(smem + (kt % 3) * STAGE_BYTES);
        const uint32_t* Bs = reinterpret_cast<const uint32_t*>(smem + (kt % 3) * STAGE_BYTES + ABYTES);

#pragma unroll
        for (int ks = 0; ks < BK; ks += 8) {
            uint32_t af[4][4];
#pragma unroll
            for (int i = 0; i < 4; i++) {
                const int r = wm + i * 16 + g;
                af[i][0] = As[r * ASTR + ks + tg];
                af[i][1] = As[(r + 8) * ASTR + ks + tg];
                af[i][2] = As[r * ASTR + ks + tg + 4];
                af[i][3] = As[(r + 8) * ASTR + ks + tg + 4];
            }
            uint32_t bf[8][2];
#pragma unroll
            for (int j = 0; j < 8; j++) {
                bf[j][0] = Bs[(ks + tg) * BSTR + wn + j * 8 + g];
                bf[j][1] = Bs[(ks + tg + 4) * BSTR + wn + j * 8 + g];
            }
#pragma unroll
            for (int i = 0; i < 4; i++)
#pragma unroll
                for (int j = 0; j < 8; j++) mma_tf32(acc[i][j], af[i], bf[j]);
        }
    }
#undef LOAD_STAGE

    // ---- epilogue ----
#pragma unroll
    for (int i = 0; i < 4; i++) {
#pragma unroll
        for (int half = 0; half < 2; half++) {
            const int r = m0 + wm + i * 16 + g + half * 8;
            if (r < cnt) {
                if constexpr (FIRST) {
                    float* dst = &g_hidden[(size_t)(g_list[e * NSLOT + r]) * DDIM + n0 + wn];
#pragma unroll
                    for (int j = 0; j < 8; j++) {
                        float v0 = acc[i][j][half * 2 + 0];
                        float v1 = acc[i][j][half * 2 + 1];
                        v0 = v0 > 0.f ? v0 * v0 : 0.f;
                        v1 = v1 > 0.f ? v1 * v1 : 0.f;
                        uint2 o; o.x = f2tf32(v0); o.y = f2tf32(v1);
                        *reinterpret_cast<uint2*>(dst + j * 8 + 2 * tg) = o;
                    }
                } else {
                    const int packed = g_list[e * NSLOT + r];
                    const float p = g_probs[packed];
                    float* dst = &g_contrib[(size_t)packed * CDIM + n0 + wn];
#pragma unroll
                    for (int j = 0; j < 8; j++) {
                        const float v0 = p * acc[i][j][half * 2 + 0];
                        const float v1 = p * acc[i][j][half * 2 + 1];
                        *reinterpret_cast<float2*>(dst + j * 8 + 2 * tg) = make_float2(v0, v1);
                    }
                }
            }
        }
    }
}

// ---------------- combine ----------------
__global__ __launch_bounds__(256) void combine_kernel(float* __restrict__ out) {
    const int v = blockIdx.x * blockDim.x + threadIdx.x;
    const float4* __restrict__ c4 = reinterpret_cast<const float4*>(g_contrib);
    const int t = v >> 8;
    const int cc = v & 255;
    const float4 a = c4[(size_t)(t * 2) * 256 + cc];
    const float4 b = c4[(size_t)(t * 2 + 1) * 256 + cc];
    reinterpret_cast<float4*>(out)[v] = make_float4(a.x + b.x, a.y + b.y, a.z + b.z, a.w + b.w);
}

// ---------------- launch ----------------
extern "C" void kernel_launch(void* const* d_in, const int* in_sizes, int n_in,
                              void* d_out, int out_size) {
    const float* x  = (const float*)d_in[0];
    const float* rw = (const float*)d_in[1];
    const float* w1 = (const float*)d_in[2];
    const float* w2 = (const float*)d_in[3];
    float* out = (float*)d_out;

    cudaFuncSetAttribute(moe_gemm<true>,  cudaFuncAttributeMaxDynamicSharedMemorySize, SMEM_TOTAL);
    cudaFuncSetAttribute(moe_gemm<false>, cudaFuncAttributeMaxDynamicSharedMemorySize, SMEM_TOTAL);

    zero_kernel<<<1, 32>>>();
    router_kernel<<<NTOK / 8, 256>>>(x, rw);
    round_x_kernel<<<NTOK * CDIM / 4 / 256, 256>>>(x);
    round_w_kernel<<<NEXP * CDIM * DDIM / 4 / 256, 256>>>(w1, 0);
    round_w_kernel<<<NEXP * DDIM * CDIM / 4 / 256, 256>>>(w2, 1);

    dim3 grid(DDIM / BN, NSLOT / BM, NEXP);  // (8, 128, 8); blocks past cnt[e] exit early
    moe_gemm<true><<<grid, 128, SMEM_TOTAL>>>();
    moe_gemm<false><<<grid, 128, SMEM_TOTAL>>>();

    combine_kernel<<<NTOK * CDIM / 4 / 256, 256>>>(out);
}